// round 13
// baseline (speedup 1.0000x reference)
#include <cuda_runtime.h>
#include <cstdint>

#define VOCAB 256
#define D 512
#define A 64
#define BB 8
#define LL 2048
#define LN_EPS 1e-5f

// ---------------- scratch (device globals; no allocations) ----------------
__device__ float4 g_h4[VOCAB * 128];       // h row-major: [v][d/4]
__device__ float g_q[VOCAB * A];
__device__ float g_kT[A * VOCAB];
__device__ float g_gate[VOCAB];
__device__ float g_logit[VOCAB * VOCAB];
__device__ float g_vprob[VOCAB * VOCAB];
__device__ float g_score[VOCAB * VOCAB];
__device__ float g_cnt[BB * VOCAB];

// ---------------- reduction helpers ----------------
__device__ __forceinline__ float warpSum(float v) {
    #pragma unroll
    for (int o = 16; o > 0; o >>= 1) v += __shfl_xor_sync(0xFFFFFFFFu, v, o);
    return v;
}
__device__ __forceinline__ float warpMax(float v) {
    #pragma unroll
    for (int o = 16; o > 0; o >>= 1) v = fmaxf(v, __shfl_xor_sync(0xFFFFFFFFu, v, o));
    return v;
}
__device__ __forceinline__ float blockSum256(float v, float* sh) {
    int w = threadIdx.x >> 5, l = threadIdx.x & 31;
    v = warpSum(v);
    if (l == 0) sh[w] = v;
    __syncthreads();
    if (w == 0) {
        float x = (l < 8) ? sh[l] : 0.f;
        x = warpSum(x);
        if (l == 0) sh[0] = x;
    }
    __syncthreads();
    float r = sh[0];
    __syncthreads();
    return r;
}
__device__ __forceinline__ float blockMax256(float v, float* sh) {
    int w = threadIdx.x >> 5, l = threadIdx.x & 31;
    v = warpMax(v);
    if (l == 0) sh[w] = v;
    __syncthreads();
    if (w == 0) {
        float x = (l < 8) ? sh[l] : -1e30f;
        x = warpMax(x);
        if (l == 0) sh[0] = x;
    }
    __syncthreads();
    float r = sh[0];
    __syncthreads();
    return r;
}

// ---------------- k_hn: histogram (blocks 0-7) + LN once (blocks 8-39) ----
__global__ void __launch_bounds__(256)
k_hn(const int* __restrict__ tokens, const int* __restrict__ plen,
     const float* __restrict__ E,
     const float* __restrict__ eg, const float* __restrict__ eb,
     const float* __restrict__ fg, const float* __restrict__ fb) {
    int tid = threadIdx.x, w = tid >> 5, l = tid & 31;

    if (blockIdx.x < 8) {
        int b = blockIdx.x;
        __shared__ int c[VOCAB];
        c[tid] = 0;
        __syncthreads();
        int P = plen[b];
        #pragma unroll
        for (int it = 0; it < 8; it++) {
            int i = it * 256 + tid;
            int tk = tokens[b * LL + i];
            if (i < P && tk != 0) atomicAdd(&c[tk & 255], 1);
        }
        __syncthreads();
        g_cnt[b * VOCAB + tid] = (float)c[tid];
        return;
    }

    int v = (blockIdx.x - 8) * 8 + w;
    const float4* E4 = (const float4*)E;
    float4 ef[4];
    #pragma unroll
    for (int j = 0; j < 4; j++) ef[j] = E4[v * 128 + l + 32 * j];
    float s = 0.f;
    #pragma unroll
    for (int j = 0; j < 4; j++) s += ef[j].x + ef[j].y + ef[j].z + ef[j].w;
    float mu = warpSum(s) * (1.f / D);
    float vv = 0.f;
    #pragma unroll
    for (int j = 0; j < 4; j++) {
        ef[j].x -= mu; ef[j].y -= mu; ef[j].z -= mu; ef[j].w -= mu;
        vv += ef[j].x * ef[j].x + ef[j].y * ef[j].y
            + ef[j].z * ef[j].z + ef[j].w * ef[j].w;
    }
    float inv = rsqrtf(warpSum(vv) * (1.f / D) + LN_EPS);
    {
        const float4* G = (const float4*)eg;
        const float4* Bv = (const float4*)eb;
        #pragma unroll
        for (int j = 0; j < 4; j++) {
            float4 g4 = G[l + 32 * j], b4 = Bv[l + 32 * j];
            ef[j].x = ef[j].x * inv * g4.x + b4.x;
            ef[j].y = ef[j].y * inv * g4.y + b4.y;
            ef[j].z = ef[j].z * inv * g4.z + b4.z;
            ef[j].w = ef[j].w * inv * g4.w + b4.w;
        }
    }
    s = 0.f;
    #pragma unroll
    for (int j = 0; j < 4; j++) s += ef[j].x + ef[j].y + ef[j].z + ef[j].w;
    mu = warpSum(s) * (1.f / D);
    vv = 0.f;
    #pragma unroll
    for (int j = 0; j < 4; j++) {
        ef[j].x -= mu; ef[j].y -= mu; ef[j].z -= mu; ef[j].w -= mu;
        vv += ef[j].x * ef[j].x + ef[j].y * ef[j].y
            + ef[j].z * ef[j].z + ef[j].w * ef[j].w;
    }
    inv = rsqrtf(warpSum(vv) * (1.f / D) + LN_EPS);
    {
        const float4* G = (const float4*)fg;
        const float4* Bv = (const float4*)fb;
        #pragma unroll
        for (int j = 0; j < 4; j++) {
            float4 g4 = G[l + 32 * j], b4 = Bv[l + 32 * j];
            float4 hv;
            hv.x = ef[j].x * inv * g4.x + b4.x;
            hv.y = ef[j].y * inv * g4.y + b4.y;
            hv.z = ef[j].z * inv * g4.z + b4.z;
            hv.w = ef[j].w * inv * g4.w + b4.w;
            g_h4[v * 128 + l + 32 * j] = hv;
        }
    }
}

// ---------------- k_proj: 800 blocks, loads h tile coalesced --------------
__global__ void __launch_bounds__(256)
k_proj(const float* __restrict__ E,
       const float* __restrict__ qw, const float* __restrict__ qb,
       const float* __restrict__ kw, const float* __restrict__ kb,
       const float* __restrict__ gw, const float* __restrict__ gb) {
    int tid = threadIdx.x, w = tid >> 5, l = tid & 31;
    int pb = blockIdx.x;
    int v0 = (pb & 31) * 8;
    int obase = (pb >> 5) * 16;
    __shared__ __align__(16) float4 hs4[8 * 128];

    int olist[2];
    bool oval[2];
    float bias[2];
    const float4* wrow4[2];
    #pragma unroll
    for (int oi = 0; oi < 2; oi++) {
        int o = obase + w * 2 + oi;
        oval[oi] = (o <= 384);
        int oe = oval[oi] ? o : 384;
        olist[oi] = oe;
        const float* wr;
        if (oe < 256)      { wr = E + oe * D;          bias[oi] = 0.f; }
        else if (oe < 320) { wr = qw + (oe - 256) * D; bias[oi] = qb[oe - 256]; }
        else if (oe < 384) { wr = kw + (oe - 320) * D; bias[oi] = kb[oe - 320]; }
        else               { wr = gw;                  bias[oi] = gb[0]; }
        wrow4[oi] = (const float4*)wr;
    }
    float4 e4[2][4];
    #pragma unroll
    for (int oi = 0; oi < 2; oi++)
        #pragma unroll
        for (int jj = 0; jj < 4; jj++)
            e4[oi][jj] = wrow4[oi][l + 32 * jj];

    #pragma unroll
    for (int i = 0; i < 4; i++)
        hs4[tid + 256 * i] = g_h4[v0 * 128 + tid + 256 * i];
    __syncthreads();

    float acc[8][2];
    #pragma unroll
    for (int r = 0; r < 8; r++) { acc[r][0] = 0.f; acc[r][1] = 0.f; }

    #pragma unroll
    for (int r = 0; r < 8; r++) {
        #pragma unroll
        for (int jj = 0; jj < 4; jj++) {
            float4 h4 = hs4[r * 128 + l + 32 * jj];
            #pragma unroll
            for (int oi = 0; oi < 2; oi++) {
                acc[r][oi] += e4[oi][jj].x * h4.x + e4[oi][jj].y * h4.y
                            + e4[oi][jj].z * h4.z + e4[oi][jj].w * h4.w;
            }
        }
    }

    #pragma unroll
    for (int oi = 0; oi < 2; oi++) {
        #pragma unroll
        for (int r = 0; r < 8; r++) {
            float s = warpSum(acc[r][oi]);
            if (l == 0 && oval[oi]) {
                int o = olist[oi];
                int v = v0 + r;
                if (o < 256)      g_logit[v * VOCAB + o] = s;
                else if (o < 320) g_q[v * A + (o - 256)] = s + bias[oi];
                else if (o < 384) g_kT[(o - 320) * VOCAB + v] = s + bias[oi];
                else              g_gate[v] = 1.f / (1.f + __expf(-(s + bias[oi])));
            }
        }
    }
}

// ---------------- k_sm: vocab softmax + score row per qv ------------------
__global__ void __launch_bounds__(256)
k_sm() {
    int qv = blockIdx.x, tid = threadIdx.x;
    __shared__ float red[8];
    __shared__ float qs[A];
    float lo = g_logit[qv * VOCAB + tid];
    if (tid < A) qs[tid] = g_q[qv * A + tid];
    __syncthreads();
    float s = 0.f;
    #pragma unroll
    for (int d = 0; d < A; d++) s += qs[d] * g_kT[d * VOCAB + tid];
    g_score[qv * VOCAB + tid] = s * 0.125f;
    float m = blockMax256(lo, red);
    float e = __expf(lo - m);
    float Z = blockSum256(e, red);
    g_vprob[qv * VOCAB + tid] = e * __frcp_rn(Z);
}

// ---------------- k_write: transposed-LUT writer ---------------------------
// lutT[v] = 16 floats = lut[0..15][v], stored as 4 float4s at stride 5
// (5 odd -> conflict-free construction; 80B row stride keeps 16B alignment).
// Row 256 = zeros (sentinel for masked positions).
__global__ void __launch_bounds__(256)
k_write(const int* __restrict__ tokens, const int* __restrict__ plen,
        float* __restrict__ out, int has_gate, int has_attn) {
    int b = blockIdx.y, t0 = blockIdx.x * 16, tid = threadIdx.x;
    int w = tid >> 5, l = tid & 31;
    __shared__ __align__(16) float4 lutT4[257 * 5];
    __shared__ float scnt[VOCAB];
    __shared__ float mxs[16], izs[16], gts[16];
    __shared__ int qvs[16];

    int P = plen[b];
    scnt[tid] = g_cnt[b * VOCAB + tid];
    if (tid < 16) qvs[tid] = tokens[b * LL + t0 + tid] & 255;   // raw query toks

    // clamped tokens for this thread's two float4-columns (registers only)
    const int4* tg = (const int4*)(tokens + b * LL);
    int4 tkA = tg[tid], tkB = tg[tid + 256];
    {
        int sA = tid * 4, sB = (tid + 256) * 4;
        tkA.x = (sA + 0 < P) ? (tkA.x & 255) : 256;
        tkA.y = (sA + 1 < P) ? (tkA.y & 255) : 256;
        tkA.z = (sA + 2 < P) ? (tkA.z & 255) : 256;
        tkA.w = (sA + 3 < P) ? (tkA.w & 255) : 256;
        tkB.x = (sB + 0 < P) ? (tkB.x & 255) : 256;
        tkB.y = (sB + 1 < P) ? (tkB.y & 255) : 256;
        tkB.z = (sB + 2 < P) ? (tkB.z & 255) : 256;
        tkB.w = (sB + 3 < P) ? (tkB.w & 255) : 256;
    }
    __syncthreads();

    // ---- step 1: per-row softmax stats (warp w does rows w and w+8) ----
    #pragma unroll
    for (int jj = 0; jj < 2; jj++) {
        int j = w + jj * 8;
        int qv = qvs[j];
        float sv[8], cf[8];
        float mx = -1e30f;
        #pragma unroll
        for (int m = 0; m < 8; m++) {
            int v = l + 32 * m;
            sv[m] = g_score[qv * VOCAB + v];
            cf[m] = scnt[v];
            mx = fmaxf(mx, cf[m] > 0.f ? sv[m] : -1e30f);
        }
        mx = warpMax(mx);
        float z = 0.f;
        #pragma unroll
        for (int m = 0; m < 8; m++) z += cf[m] * __expf(sv[m] - mx);
        z = warpSum(z);
        if (l == 0) { mxs[j] = mx; izs[j] = __frcp_rn(z); }
    }
    if (tid < 16) gts[tid] = g_gate[qvs[tid]];
    __syncthreads();

    // ---- step 2: thread v fills lutT row v (all 16 j) ----
    {
        int v = tid;
        float4 r[4];
        float* rf = (float*)r;
        #pragma unroll
        for (int j = 0; j < 16; j++) {
            float sv = g_score[qvs[j] * VOCAB + v];
            float at = __expf(sv - mxs[j]) * izs[j];
            rf[j] = (v == 0) ? 0.f : at;      // PAD column masked
        }
        #pragma unroll
        for (int c = 0; c < 4; c++) lutT4[v * 5 + c] = r[c];
        if (tid < 4) lutT4[256 * 5 + tid] = make_float4(0.f, 0.f, 0.f, 0.f);
    }
    __syncthreads();

    float* out_lm   = out;
    float* out_gate = out + (size_t)BB * LL * VOCAB;
    float* out_attn = out_gate + (size_t)BB * LL;

    if (has_gate && tid < 16) out_gate[b * LL + t0 + tid] = gts[tid];

    // ---- LM: 4x4 transposed tiles, float4 everywhere ----
    {
        int c = tid & 63;              // float4-column 0..63
        int jg = tid >> 6;             // row group 0..3
        float4 L0 = lutT4[(4 * c + 0) * 5 + jg];
        float4 L1 = lutT4[(4 * c + 1) * 5 + jg];
        float4 L2 = lutT4[(4 * c + 2) * 5 + jg];
        float4 L3 = lutT4[(4 * c + 3) * 5 + jg];
        float4 cn4 = ((const float4*)scnt)[c];
        float lj[4][4] = {
            {L0.x, L1.x, L2.x, L3.x},
            {L0.y, L1.y, L2.y, L3.y},
            {L0.z, L1.z, L2.z, L3.z},
            {L0.w, L1.w, L2.w, L3.w},
        };
        #pragma unroll
        for (int k = 0; k < 4; k++) {
            int j = jg * 4 + k;
            int qv = qvs[j];
            float gt = gts[j], og = 1.f - gt;
            float4 pv = ((const float4*)(g_vprob + qv * VOCAB))[c];
            float4 m4;
            m4.x = __logf(fmaxf(gt * pv.x + og * (cn4.x * lj[k][0]), 1e-12f));
            m4.y = __logf(fmaxf(gt * pv.y + og * (cn4.y * lj[k][1]), 1e-12f));
            m4.z = __logf(fmaxf(gt * pv.z + og * (cn4.z * lj[k][2]), 1e-12f));
            m4.w = __logf(fmaxf(gt * pv.w + og * (cn4.w * lj[k][3]), 1e-12f));
            __stcs((float4*)(out_lm + ((size_t)(b * LL + t0 + j)) * VOCAB) + c, m4);
        }
    }

    // ---- attn: vectorized gather + 4x4 register transpose ----
    if (has_attn) {
        #pragma unroll
        for (int half = 0; half < 2; half++) {
            int4 tk = half ? tkB : tkA;
            int colf = tid + half * 256;    // float4-column index 0..511
            #pragma unroll
            for (int jg = 0; jg < 4; jg++) {
                float4 c0 = lutT4[tk.x * 5 + jg];
                float4 c1 = lutT4[tk.y * 5 + jg];
                float4 c2 = lutT4[tk.z * 5 + jg];
                float4 c3 = lutT4[tk.w * 5 + jg];
                float* base = out_attn + ((size_t)(b * LL + t0 + jg * 4)) * LL;
                float4 r0 = {c0.x, c1.x, c2.x, c3.x};
                float4 r1 = {c0.y, c1.y, c2.y, c3.y};
                float4 r2 = {c0.z, c1.z, c2.z, c3.z};
                float4 r3 = {c0.w, c1.w, c2.w, c3.w};
                __stcs((float4*)(base) + colf, r0);
                __stcs((float4*)(base + LL) + colf, r1);
                __stcs((float4*)(base + 2 * LL) + colf, r2);
                __stcs((float4*)(base + 3 * LL) + colf, r3);
            }
        }
    }
}

// ---------------- launch ----------------
extern "C" void kernel_launch(void* const* d_in, const int* in_sizes, int n_in,
                              void* d_out, int out_size) {
    const int*   tokens = (const int*)d_in[0];
    const int*   plen   = (const int*)d_in[1];
    const float* E      = (const float*)d_in[2];
    const float* en_g   = (const float*)d_in[3];
    const float* en_b   = (const float*)d_in[4];
    const float* fn_g   = (const float*)d_in[5];
    const float* fn_b   = (const float*)d_in[6];
    const float* q_w    = (const float*)d_in[7];
    const float* q_b    = (const float*)d_in[8];
    const float* k_w    = (const float*)d_in[9];
    const float* k_b    = (const float*)d_in[10];
    const float* g_w    = (const float*)d_in[11];
    const float* g_b    = (const float*)d_in[12];

    const long long lm_sz   = (long long)BB * LL * VOCAB;
    const long long gate_sz = (long long)BB * LL;
    const long long attn_sz = (long long)BB * LL * LL;
    int has_gate = (out_size >= lm_sz + gate_sz) ? 1 : 0;
    int has_attn = (out_size >= lm_sz + gate_sz + attn_sz) ? 1 : 0;

    k_hn   <<<40, 256>>>(tokens, plen, E, en_g, en_b, fn_g, fn_b);
    k_proj <<<25 * 32, 256>>>(E, q_w, q_b, k_w, k_b, g_w, g_b);
    k_sm   <<<VOCAB, 256>>>();
    k_write<<<dim3(LL / 16, BB), 256>>>(tokens, plen, (float*)d_out, has_gate, has_attn);
}

// round 14
// speedup vs baseline: 1.6160x; 1.6160x over previous
#include <cuda_runtime.h>
#include <cstdint>

#define VOCAB 256
#define D 512
#define A 64
#define BB 8
#define LL 2048
#define LN_EPS 1e-5f
#define LUTW 264   // lut row stride: 256 real cols + sentinel(256)=0 + pad

// ---------------- scratch (device globals; no allocations) ----------------
__device__ float4 g_h4[VOCAB * 128];       // h row-major: [v][d/4]
__device__ float g_q[VOCAB * A];
__device__ float g_kT[A * VOCAB];
__device__ float g_gate[VOCAB];
__device__ float g_logit[VOCAB * VOCAB];
__device__ float g_vprob[VOCAB * VOCAB];
__device__ float g_score[VOCAB * VOCAB];
__device__ float g_cnt[BB * VOCAB];

// ---------------- reduction helpers ----------------
__device__ __forceinline__ float warpSum(float v) {
    #pragma unroll
    for (int o = 16; o > 0; o >>= 1) v += __shfl_xor_sync(0xFFFFFFFFu, v, o);
    return v;
}
__device__ __forceinline__ float warpMax(float v) {
    #pragma unroll
    for (int o = 16; o > 0; o >>= 1) v = fmaxf(v, __shfl_xor_sync(0xFFFFFFFFu, v, o));
    return v;
}
__device__ __forceinline__ float blockSum256(float v, float* sh) {
    int w = threadIdx.x >> 5, l = threadIdx.x & 31;
    v = warpSum(v);
    if (l == 0) sh[w] = v;
    __syncthreads();
    if (w == 0) {
        float x = (l < 8) ? sh[l] : 0.f;
        x = warpSum(x);
        if (l == 0) sh[0] = x;
    }
    __syncthreads();
    float r = sh[0];
    __syncthreads();
    return r;
}
__device__ __forceinline__ float blockMax256(float v, float* sh) {
    int w = threadIdx.x >> 5, l = threadIdx.x & 31;
    v = warpMax(v);
    if (l == 0) sh[w] = v;
    __syncthreads();
    if (w == 0) {
        float x = (l < 8) ? sh[l] : -1e30f;
        x = warpMax(x);
        if (l == 0) sh[0] = x;
    }
    __syncthreads();
    float r = sh[0];
    __syncthreads();
    return r;
}

// ---------------- k_hn: histogram (blocks 0-7) + LN once (blocks 8-39) ----
__global__ void __launch_bounds__(256)
k_hn(const int* __restrict__ tokens, const int* __restrict__ plen,
     const float* __restrict__ E,
     const float* __restrict__ eg, const float* __restrict__ eb,
     const float* __restrict__ fg, const float* __restrict__ fb) {
    int tid = threadIdx.x, w = tid >> 5, l = tid & 31;

    if (blockIdx.x < 8) {
        int b = blockIdx.x;
        __shared__ int c[VOCAB];
        c[tid] = 0;
        __syncthreads();
        int P = plen[b];
        #pragma unroll
        for (int it = 0; it < 8; it++) {
            int i = it * 256 + tid;
            int tk = tokens[b * LL + i];
            if (i < P && tk != 0) atomicAdd(&c[tk & 255], 1);
        }
        __syncthreads();
        g_cnt[b * VOCAB + tid] = (float)c[tid];
        return;
    }

    int v = (blockIdx.x - 8) * 8 + w;
    const float4* E4 = (const float4*)E;
    float4 ef[4];
    #pragma unroll
    for (int j = 0; j < 4; j++) ef[j] = E4[v * 128 + l + 32 * j];
    float s = 0.f;
    #pragma unroll
    for (int j = 0; j < 4; j++) s += ef[j].x + ef[j].y + ef[j].z + ef[j].w;
    float mu = warpSum(s) * (1.f / D);
    float vv = 0.f;
    #pragma unroll
    for (int j = 0; j < 4; j++) {
        ef[j].x -= mu; ef[j].y -= mu; ef[j].z -= mu; ef[j].w -= mu;
        vv += ef[j].x * ef[j].x + ef[j].y * ef[j].y
            + ef[j].z * ef[j].z + ef[j].w * ef[j].w;
    }
    float inv = rsqrtf(warpSum(vv) * (1.f / D) + LN_EPS);
    {
        const float4* G = (const float4*)eg;
        const float4* Bv = (const float4*)eb;
        #pragma unroll
        for (int j = 0; j < 4; j++) {
            float4 g4 = G[l + 32 * j], b4 = Bv[l + 32 * j];
            ef[j].x = ef[j].x * inv * g4.x + b4.x;
            ef[j].y = ef[j].y * inv * g4.y + b4.y;
            ef[j].z = ef[j].z * inv * g4.z + b4.z;
            ef[j].w = ef[j].w * inv * g4.w + b4.w;
        }
    }
    s = 0.f;
    #pragma unroll
    for (int j = 0; j < 4; j++) s += ef[j].x + ef[j].y + ef[j].z + ef[j].w;
    mu = warpSum(s) * (1.f / D);
    vv = 0.f;
    #pragma unroll
    for (int j = 0; j < 4; j++) {
        ef[j].x -= mu; ef[j].y -= mu; ef[j].z -= mu; ef[j].w -= mu;
        vv += ef[j].x * ef[j].x + ef[j].y * ef[j].y
            + ef[j].z * ef[j].z + ef[j].w * ef[j].w;
    }
    inv = rsqrtf(warpSum(vv) * (1.f / D) + LN_EPS);
    {
        const float4* G = (const float4*)fg;
        const float4* Bv = (const float4*)fb;
        #pragma unroll
        for (int j = 0; j < 4; j++) {
            float4 g4 = G[l + 32 * j], b4 = Bv[l + 32 * j];
            float4 hv;
            hv.x = ef[j].x * inv * g4.x + b4.x;
            hv.y = ef[j].y * inv * g4.y + b4.y;
            hv.z = ef[j].z * inv * g4.z + b4.z;
            hv.w = ef[j].w * inv * g4.w + b4.w;
            g_h4[v * 128 + l + 32 * j] = hv;
        }
    }
}

// ---------------- k_proj: 800 blocks, loads h tile coalesced --------------
__global__ void __launch_bounds__(256)
k_proj(const float* __restrict__ E,
       const float* __restrict__ qw, const float* __restrict__ qb,
       const float* __restrict__ kw, const float* __restrict__ kb,
       const float* __restrict__ gw, const float* __restrict__ gb) {
    int tid = threadIdx.x, w = tid >> 5, l = tid & 31;
    int pb = blockIdx.x;
    int v0 = (pb & 31) * 8;
    int obase = (pb >> 5) * 16;
    __shared__ __align__(16) float4 hs4[8 * 128];

    int olist[2];
    bool oval[2];
    float bias[2];
    const float4* wrow4[2];
    #pragma unroll
    for (int oi = 0; oi < 2; oi++) {
        int o = obase + w * 2 + oi;
        oval[oi] = (o <= 384);
        int oe = oval[oi] ? o : 384;
        olist[oi] = oe;
        const float* wr;
        if (oe < 256)      { wr = E + oe * D;          bias[oi] = 0.f; }
        else if (oe < 320) { wr = qw + (oe - 256) * D; bias[oi] = qb[oe - 256]; }
        else if (oe < 384) { wr = kw + (oe - 320) * D; bias[oi] = kb[oe - 320]; }
        else               { wr = gw;                  bias[oi] = gb[0]; }
        wrow4[oi] = (const float4*)wr;
    }
    float4 e4[2][4];
    #pragma unroll
    for (int oi = 0; oi < 2; oi++)
        #pragma unroll
        for (int jj = 0; jj < 4; jj++)
            e4[oi][jj] = wrow4[oi][l + 32 * jj];

    #pragma unroll
    for (int i = 0; i < 4; i++)
        hs4[tid + 256 * i] = g_h4[v0 * 128 + tid + 256 * i];
    __syncthreads();

    float acc[8][2];
    #pragma unroll
    for (int r = 0; r < 8; r++) { acc[r][0] = 0.f; acc[r][1] = 0.f; }

    #pragma unroll
    for (int r = 0; r < 8; r++) {
        #pragma unroll
        for (int jj = 0; jj < 4; jj++) {
            float4 h4 = hs4[r * 128 + l + 32 * jj];
            #pragma unroll
            for (int oi = 0; oi < 2; oi++) {
                acc[r][oi] += e4[oi][jj].x * h4.x + e4[oi][jj].y * h4.y
                            + e4[oi][jj].z * h4.z + e4[oi][jj].w * h4.w;
            }
        }
    }

    #pragma unroll
    for (int oi = 0; oi < 2; oi++) {
        #pragma unroll
        for (int r = 0; r < 8; r++) {
            float s = warpSum(acc[r][oi]);
            if (l == 0 && oval[oi]) {
                int o = olist[oi];
                int v = v0 + r;
                if (o < 256)      g_logit[v * VOCAB + o] = s;
                else if (o < 320) g_q[v * A + (o - 256)] = s + bias[oi];
                else if (o < 384) g_kT[(o - 320) * VOCAB + v] = s + bias[oi];
                else              g_gate[v] = 1.f / (1.f + __expf(-(s + bias[oi])));
            }
        }
    }
}

// ---------------- k_sm: vocab softmax + score row per qv ------------------
__global__ void __launch_bounds__(256)
k_sm() {
    int qv = blockIdx.x, tid = threadIdx.x;
    __shared__ float red[8];
    __shared__ float qs[A];
    float lo = g_logit[qv * VOCAB + tid];
    if (tid < A) qs[tid] = g_q[qv * A + tid];
    __syncthreads();
    float s = 0.f;
    #pragma unroll
    for (int d = 0; d < A; d++) s += qs[d] * g_kT[d * VOCAB + tid];
    g_score[qv * VOCAB + tid] = s * 0.125f;
    float m = blockMax256(lo, red);
    float e = __expf(lo - m);
    float Z = blockSum256(e, red);
    g_vprob[qv * VOCAB + tid] = e * __frcp_rn(Z);
}

// ---------------- k_write: round-12 writer, reg-resident tokens, vec LM ---
__global__ void __launch_bounds__(256)
k_write(const int* __restrict__ tokens, const int* __restrict__ plen,
        float* __restrict__ out, int has_gate, int has_attn) {
    int b = blockIdx.y, t0 = blockIdx.x * 16, tid = threadIdx.x;
    int w = tid >> 5, l = tid & 31;
    __shared__ float lut[16][LUTW];
    __shared__ float scnt[VOCAB];
    __shared__ float gts[16];
    __shared__ int qvs[16];

    int P = plen[b];
    scnt[tid] = g_cnt[b * VOCAB + tid];
    if (tid < 16) {
        int qv = tokens[b * LL + t0 + tid] & 255;   // raw query tokens
        qvs[tid] = qv;
        gts[tid] = g_gate[qv];
    }

    // clamped tokens kept in registers (sentinel 256 for masked positions)
    const int4* tg = (const int4*)(tokens + b * LL);
    int4 tkA = tg[tid], tkB = tg[tid + 256];
    {
        int sA = tid * 4, sB = (tid + 256) * 4;
        tkA.x = (sA + 0 < P) ? (tkA.x & 255) : 256;
        tkA.y = (sA + 1 < P) ? (tkA.y & 255) : 256;
        tkA.z = (sA + 2 < P) ? (tkA.z & 255) : 256;
        tkA.w = (sA + 3 < P) ? (tkA.w & 255) : 256;
        tkB.x = (sB + 0 < P) ? (tkB.x & 255) : 256;
        tkB.y = (sB + 1 < P) ? (tkB.y & 255) : 256;
        tkB.z = (sB + 2 < P) ? (tkB.z & 255) : 256;
        tkB.w = (sB + 3 < P) ? (tkB.w & 255) : 256;
    }
    __syncthreads();

    // ---- AT rows: warp w computes rows w and w+8 (shuffles only) ----
    #pragma unroll
    for (int jj = 0; jj < 2; jj++) {
        int j = w + jj * 8;
        int qv = qvs[j];
        float sv[8], cf[8];
        float mx = -1e30f;
        #pragma unroll
        for (int m = 0; m < 8; m++) {
            int v = l + 32 * m;
            sv[m] = g_score[qv * VOCAB + v];
            cf[m] = scnt[v];
            mx = fmaxf(mx, cf[m] > 0.f ? sv[m] : -1e30f);
        }
        mx = warpMax(mx);
        float ex[8], z = 0.f;
        #pragma unroll
        for (int m = 0; m < 8; m++) {
            ex[m] = __expf(sv[m] - mx);
            z += cf[m] * ex[m];
        }
        z = warpSum(z);
        float invz = __frcp_rn(z);
        #pragma unroll
        for (int m = 0; m < 8; m++) {
            int v = l + 32 * m;
            float at = ex[m] * invz;
            if (v == 0) at = 0.f;            // PAD column masked
            lut[j][v] = at;
        }
        if (l == 0) lut[j][256] = 0.f;       // sentinel for s >= P
    }
    __syncthreads();

    float* out_lm   = out;
    float* out_gate = out + (size_t)BB * LL * VOCAB;
    float* out_attn = out_gate + (size_t)BB * LL;

    if (has_gate && tid < 16) out_gate[b * LL + t0 + tid] = gts[tid];

    // ---- LM: vectorized, thread = (col-group, row-group), 4 rows each ----
    {
        int c = tid & 63;              // float4 column 0..63
        int jg = tid >> 6;             // row group 0..3
        float4 cn4 = ((const float4*)scnt)[c];
        #pragma unroll
        for (int k = 0; k < 4; k++) {
            int j = jg * 4 + k;
            int qv = qvs[j];
            float gt = gts[j], og = 1.f - gt;
            float4 lv = *(const float4*)&lut[j][4 * c];
            float4 pv = ((const float4*)(g_vprob + qv * VOCAB))[c];
            float4 m4;
            m4.x = __logf(fmaxf(gt * pv.x + og * (cn4.x * lv.x), 1e-12f));
            m4.y = __logf(fmaxf(gt * pv.y + og * (cn4.y * lv.y), 1e-12f));
            m4.z = __logf(fmaxf(gt * pv.z + og * (cn4.z * lv.z), 1e-12f));
            m4.w = __logf(fmaxf(gt * pv.w + og * (cn4.w * lv.w), 1e-12f));
            __stcs((float4*)(out_lm + ((size_t)(b * LL + t0 + j)) * VOCAB) + c, m4);
        }
    }

    // ---- attn streaming: branch-free scalar gather (proven fastest) ----
    if (has_attn) {
        #pragma unroll
        for (int j = 0; j < 16; j++) {
            const float* L = lut[j];
            float4* orow = (float4*)(out_attn + ((size_t)(b * LL + t0 + j)) * LL);
            float4 o;
            o.x = L[tkA.x]; o.y = L[tkA.y]; o.z = L[tkA.z]; o.w = L[tkA.w];
            __stcs(orow + tid, o);
            o.x = L[tkB.x]; o.y = L[tkB.y]; o.z = L[tkB.z]; o.w = L[tkB.w];
            __stcs(orow + 256 + tid, o);
        }
    }
}

// ---------------- launch ----------------
extern "C" void kernel_launch(void* const* d_in, const int* in_sizes, int n_in,
                              void* d_out, int out_size) {
    const int*   tokens = (const int*)d_in[0];
    const int*   plen   = (const int*)d_in[1];
    const float* E      = (const float*)d_in[2];
    const float* en_g   = (const float*)d_in[3];
    const float* en_b   = (const float*)d_in[4];
    const float* fn_g   = (const float*)d_in[5];
    const float* fn_b   = (const float*)d_in[6];
    const float* q_w    = (const float*)d_in[7];
    const float* q_b    = (const float*)d_in[8];
    const float* k_w    = (const float*)d_in[9];
    const float* k_b    = (const float*)d_in[10];
    const float* g_w    = (const float*)d_in[11];
    const float* g_b    = (const float*)d_in[12];

    const long long lm_sz   = (long long)BB * LL * VOCAB;
    const long long gate_sz = (long long)BB * LL;
    const long long attn_sz = (long long)BB * LL * LL;
    int has_gate = (out_size >= lm_sz + gate_sz) ? 1 : 0;
    int has_attn = (out_size >= lm_sz + gate_sz + attn_sz) ? 1 : 0;

    k_hn   <<<40, 256>>>(tokens, plen, E, en_g, en_b, fn_g, fn_b);
    k_proj <<<25 * 32, 256>>>(E, q_w, q_b, k_w, k_b, g_w, g_b);
    k_sm   <<<VOCAB, 256>>>();
    k_write<<<dim3(LL / 16, BB), 256>>>(tokens, plen, (float*)d_out, has_gate, has_attn);
}